// round 12
// baseline (speedup 1.0000x reference)
#include <cuda_runtime.h>

// SumLayer: out = node_mars with rows nids replaced by
//           log(sum_c params[pids[g,c]] * exp(element_mars[cids[g,c]]))
// G=8192 groups, C=64 children, B=128 batch, 16384 rows.
//
// R12 = R11 (2 warps/group, float2, 8-deep prefetch, 89% occ, 31.2us) with
// the burst pipeline converted to a SUSTAINED one: rotated register double
// buffer x[2][8] -> batch k+1 is issued BEFORE batch k is consumed, so each
// warp keeps ~2KB continuously in flight instead of alternating burst/stall.
// cids/pids (read once per replay) are loaded evict-first (__ldcs) to
// protect element_mars L2 residency across graph replays.
// Copy path: interpolation probe on sorted nids. No-max LSE verified safe.

#define FULL 0xffffffffu
#define B2 64               // 128 floats = 64 float2 per row

__global__ __launch_bounds__(128)
void sumlayer_kernel(const float2* __restrict__ em,      // element_mars
                     const float*  __restrict__ params,
                     const int*    __restrict__ nids,
                     const int*    __restrict__ cids,    // [G,64]
                     const int*    __restrict__ pids,    // [G,64]
                     const float4* __restrict__ nm,      // node_mars
                     float4*       __restrict__ out,
                     int G, int nrows) {
    int warp = (blockIdx.x * blockDim.x + threadIdx.x) >> 5;
    int lane = threadIdx.x & 31;
    int nCompute = 2 * G;

    if (warp >= nCompute) {
        // ---------- copy path: one warp per row ----------
        int row = warp - nCompute;
        if (row >= nrows) return;
        // membership in sorted nids: interpolation probe (exact when
        // nids=arange -> 1 load), binary-search fallback for generality.
        int lo = 0, hi = G - 1;
        bool found = false;
        int p = row <= hi ? row : hi;
        int v = __ldg(&nids[p]);
        if (v == row) found = true;
        else if (v < row) lo = p + 1;
        else hi = p - 1;
        while (!found && lo <= hi) {
            int mid = (lo + hi) >> 1;
            int u = __ldg(&nids[mid]);
            if (u == row) { found = true; break; }
            if (u < row) lo = mid + 1; else hi = mid - 1;
        }
        if (!found) {
            float4 val = __ldcs(&nm[(size_t)row * 32 + lane]);
            __stcs(&out[(size_t)row * 32 + lane], val);
        }
        return;
    }

    // ---------- compute path: TWO warps per group, half batch each ----------
    int g   = warp >> 1;
    int col = (warp & 1) * 32 + lane;            // float2 column in 64-wide row

    // 64 (cid, weight) pairs cached across lanes (evict-first: read once).
    int   cid_lo = __ldcs(&cids[g * 64 + lane]);
    int   cid_hi = __ldcs(&cids[g * 64 + 32 + lane]);
    float w_lo   = __ldg(&params[__ldcs(&pids[g * 64 + lane])]);
    float w_hi   = __ldg(&params[__ldcs(&pids[g * 64 + 32 + lane])]);

    const float2* em_c = em + col;

    float2 s0 = make_float2(0.f, 0.f);
    float2 s1 = make_float2(0.f, 0.f);

    float2 x[2][8];

    // prologue: issue batch 0 (children 0..3 from lo/hi pairs)
    #pragma unroll
    for (int j = 0; j < 4; ++j) {
        int c0 = __shfl_sync(FULL, cid_lo, j);
        int c1 = __shfl_sync(FULL, cid_hi, j);
        x[0][2 * j]     = __ldg(em_c + (size_t)c0 * B2);
        x[0][2 * j + 1] = __ldg(em_c + (size_t)c1 * B2);
    }

    #pragma unroll
    for (int step = 0; step < 8; ++step) {
        int cur = step & 1, nxt = cur ^ 1;

        // issue batch k+1 BEFORE consuming batch k (sustained in-flight)
        if (step < 7) {
            #pragma unroll
            for (int j = 0; j < 4; ++j) {
                int c = (step + 1) * 4 + j;          // compile-time constant
                int c0 = __shfl_sync(FULL, cid_lo, c);
                int c1 = __shfl_sync(FULL, cid_hi, c);
                x[nxt][2 * j]     = __ldg(em_c + (size_t)c0 * B2);
                x[nxt][2 * j + 1] = __ldg(em_c + (size_t)c1 * B2);
            }
        }

        // consume batch k: weights shfl'd here (off the address path)
        #pragma unroll
        for (int j = 0; j < 4; ++j) {
            int c = step * 4 + j;
            float wa = __shfl_sync(FULL, w_lo, c);
            float wb = __shfl_sync(FULL, w_hi, c);
            float2 va = x[cur][2 * j];
            float2 vb = x[cur][2 * j + 1];
            s0.x += wa * __expf(va.x);  s1.x += wb * __expf(vb.x);
            s0.y += wa * __expf(va.y);  s1.y += wb * __expf(vb.y);
        }
    }

    float2 o;
    o.x = __logf(s0.x + s1.x);
    o.y = __logf(s0.y + s1.y);

    int nid = __ldg(&nids[g]);
    float2* orow = (float2*)out;
    __stcs(&orow[(size_t)nid * B2 + col], o);
}

extern "C" void kernel_launch(void* const* d_in, const int* in_sizes, int n_in,
                              void* d_out, int out_size) {
    const float* node_mars    = (const float*)d_in[0];
    const float* element_mars = (const float*)d_in[1];
    const float* params       = (const float*)d_in[2];
    const int*   nids         = (const int*)d_in[3];
    const int*   cids         = (const int*)d_in[4];
    const int*   pids         = (const int*)d_in[5];
    float* out = (float*)d_out;

    int G = in_sizes[3];
    int nrows = out_size / 128;             // 16384

    int total_warps = 2 * G + nrows;        // 2 compute warps/group + copy rows
    int threads = 128;                      // 4 warps/block
    int blocks = (total_warps * 32 + threads - 1) / threads;
    sumlayer_kernel<<<blocks, threads>>>((const float2*)element_mars, params,
                                         nids, cids, pids,
                                         (const float4*)node_mars,
                                         (float4*)out, G, nrows);
}